// round 10
// baseline (speedup 1.0000x reference)
#include <cuda_runtime.h>
#include <cstdint>

#define D128 128
#define VT   32
#define MCTA 128
#define THR  512
#define EPSF 1e-8f

__device__ float g_x2[16384];
__device__ float g_c2[8192];

// smem float offsets
#define XH   0              // 128 x 132 tf32-hi X tile
#define XL   16896          // 128 x 132 tf32-lo X tile
#define CH   33792          // 32 x 132 tf32-hi C tile
#define CL   38016          // 32 x 132 tf32-lo C tile
#define WB   42240          // 32 x 136 k-major W buffer
#define C2S  46592          // 32 codeword norms
#define SMEM_FLOATS 46656   // 186,624 bytes
// end-of-kernel reuse (after main loop)
#define RS_SUM  0
#define RS_MIND 2048
#define RS_MINI 4096
#define RINV    WB

static __device__ __forceinline__ uint32_t tf32_rna(float x) {
    uint32_t r; asm("cvt.rna.tf32.f32 %0, %1;" : "=r"(r) : "f"(x)); return r;
}
static __device__ __forceinline__ uint32_t fbits(float x) { return __float_as_uint(x); }
static __device__ __forceinline__ uint32_t smem_u32(const void* p) {
    uint32_t a;
    asm("{ .reg .u64 t; cvta.to.shared.u64 t, %1; cvt.u32.u64 %0, t; }" : "=r"(a) : "l"(p));
    return a;
}

static __device__ __forceinline__ void mma8(float* d, const uint32_t* a,
                                            uint32_t b0, uint32_t b1) {
    asm volatile("mma.sync.aligned.m16n8k8.row.col.f32.tf32.tf32.f32 "
        "{%0,%1,%2,%3}, {%4,%5,%6,%7}, {%8,%9}, {%0,%1,%2,%3};"
        : "+f"(d[0]), "+f"(d[1]), "+f"(d[2]), "+f"(d[3])
        : "r"(a[0]), "r"(a[1]), "r"(a[2]), "r"(a[3]), "r"(b0), "r"(b1));
}
#define LDSM4(r, a) \
    asm volatile("ldmatrix.sync.aligned.m8n8.x4.shared.b16 {%0,%1,%2,%3}, [%4];" \
        : "=r"((r)[0]), "=r"((r)[1]), "=r"((r)[2]), "=r"((r)[3]) : "r"(a))

// -------- norms pre-kernel (one warp per row) --------
__global__ void norms_kernel(const float* __restrict__ x,
                             const float* __restrict__ cb, int n, int v) {
    int gw   = (blockIdx.x * blockDim.x + threadIdx.x) >> 5;
    int lane = threadIdx.x & 31;
    if (gw >= n + v) return;
    const float* src = (gw < n) ? (x + (size_t)gw * D128) : (cb + (size_t)(gw - n) * D128);
    float4 val = ((const float4*)src)[lane];
    float s = val.x*val.x + val.y*val.y + val.z*val.z + val.w*val.w;
    #pragma unroll
    for (int off = 16; off; off >>= 1) s += __shfl_xor_sync(0xffffffffu, s, off);
    if (lane == 0) { if (gw < n) g_x2[gw] = s; else g_c2[gw - n] = s; }
}

// -------- fused SoftVQ: ldmatrix + mma.sync tf32, precomputed X split --------
__global__ void __launch_bounds__(THR, 1) softvq_mma(
    const float* __restrict__ x, const float* __restrict__ cb,
    float* __restrict__ out_embed, float* __restrict__ out_idx, int n, int v)
{
    extern __shared__ float sm[];
    const int t   = threadIdx.x;
    const int w   = t >> 5;
    const int l   = t & 31;
    const int r0l = l >> 2;          // row within m16 block (0..7)
    const int cql = l & 3;           // quad column id
    const int g   = w >> 2;          // row-group: rows g*32 .. g*32+31
    const int q   = w & 3;           // V-quarter (GEMM1) / N-quarter (GEMM2)
    const int m0  = blockIdx.x * MCTA;

    // ---- load X tile [128x128], split tf32 hi/lo ONCE into smem ----
    #pragma unroll
    for (int i = 0; i < 8; i++) {
        int f   = i * THR + t;
        int row = f >> 5;
        int c4  = (f & 31) * 4;
        float4 xv = *(const float4*)(x + (size_t)(m0 + row) * D128 + c4);
        float h0 = __uint_as_float(tf32_rna(xv.x));
        float h1 = __uint_as_float(tf32_rna(xv.y));
        float h2 = __uint_as_float(tf32_rna(xv.z));
        float h3 = __uint_as_float(tf32_rna(xv.w));
        int base = row * 132 + c4;
        *(float4*)(sm + XH + base) = make_float4(h0, h1, h2, h3);
        *(float4*)(sm + XL + base) = make_float4(
            __uint_as_float(tf32_rna(xv.x - h0)), __uint_as_float(tf32_rna(xv.y - h1)),
            __uint_as_float(tf32_rna(xv.z - h2)), __uint_as_float(tf32_rna(xv.w - h3)));
    }

    float x2r[2][2];
    #pragma unroll
    for (int mb = 0; mb < 2; mb++) {
        x2r[mb][0] = g_x2[m0 + g * 32 + mb * 16 + r0l];
        x2r[mb][1] = g_x2[m0 + g * 32 + mb * 16 + r0l + 8];
    }

    // ---- ldmatrix lane base addresses (bytes) ----
    const uint32_t sb = smem_u32(sm);
    const int lr = l & 15;               // row within 16-row block
    const int lc = (l >> 4) * 4;         // +4 float cols for upper half lanes
    const uint32_t aX0 = sb + 4u * (uint32_t)(XH + (g * 32 +      lr) * 132 + lc);
    const uint32_t aX1 = sb + 4u * (uint32_t)(XH + (g * 32 + 16 + lr) * 132 + lc);
    // GEMM1 B: lanes 0-15 -> CH rows q*8.., lanes 16-31 -> CL rows q*8..
    const uint32_t aB0 = sb + 4u * (uint32_t)(((l < 16) ? CH : CL)
                             + (q * 8 + (l & 7)) * 132 + ((l >> 3) & 1) * 4);

    float e[2][4][4];
    #pragma unroll
    for (int mb = 0; mb < 2; mb++)
        #pragma unroll
        for (int i = 0; i < 4; i++)
            #pragma unroll
            for (int j = 0; j < 4; j++) e[mb][i][j] = 0.0f;

    float wsum[2][2] = {{0.f,0.f},{0.f,0.f}};
    float mind[2][2] = {{3.4e38f,3.4e38f},{3.4e38f,3.4e38f}};
    int   mini[2][2] = {{1<<30,1<<30},{1<<30,1<<30}};

    const int NTILES = v / VT;   // 256

    for (int tile = 0; tile < NTILES; tile++) {
        __syncthreads();   // prev tile's GEMM2 reads of CH/WB complete
        const int v0 = tile * VT;
        // ---- load C tile [32x128], split hi/lo ----
        #pragma unroll
        for (int i = 0; i < 2; i++) {
            int f   = i * THR + t;
            int row = f >> 5;
            int c4  = (f & 31) * 4;
            float4 cv = *(const float4*)(cb + (size_t)(v0 + row) * D128 + c4);
            float h0 = __uint_as_float(tf32_rna(cv.x));
            float h1 = __uint_as_float(tf32_rna(cv.y));
            float h2 = __uint_as_float(tf32_rna(cv.z));
            float h3 = __uint_as_float(tf32_rna(cv.w));
            int base = row * 132 + c4;
            *(float4*)(sm + CH + base) = make_float4(h0, h1, h2, h3);
            *(float4*)(sm + CL + base) = make_float4(
                __uint_as_float(tf32_rna(cv.x - h0)), __uint_as_float(tf32_rna(cv.y - h1)),
                __uint_as_float(tf32_rna(cv.z - h2)), __uint_as_float(tf32_rna(cv.w - h3)));
        }
        if (t < VT) sm[C2S + t] = g_c2[v0 + t];
        __syncthreads();

        // ---- GEMM1: S[32 x 8] per warp, 3 tf32 products, all ldmatrix ----
        float s[2][4];
        #pragma unroll
        for (int mb = 0; mb < 2; mb++)
            #pragma unroll
            for (int j = 0; j < 4; j++) s[mb][j] = 0.0f;

        uint32_t pX0 = aX0, pX1 = aX1, pB = aB0;
        #pragma unroll 4
        for (int kt = 0; kt < 16; kt++) {
            uint32_t ah0[4], al0[4], ah1[4], al1[4], bf[4];
            LDSM4(ah0, pX0);
            LDSM4(al0, pX0 + 4u * 16896u);
            LDSM4(ah1, pX1);
            LDSM4(al1, pX1 + 4u * 16896u);
            LDSM4(bf, pB);                 // {bh0, bh1, bl0, bl1}
            mma8(s[0], ah0, bf[0], bf[1]);
            mma8(s[1], ah1, bf[0], bf[1]);
            mma8(s[0], al0, bf[0], bf[1]);
            mma8(s[1], al1, bf[0], bf[1]);
            mma8(s[0], ah0, bf[2], bf[3]);
            mma8(s[1], ah1, bf[2], bf[3]);
            pX0 += 32; pX1 += 32; pB += 32;
        }

        // ---- epilogue: d, min/sum, W -> tf32 k-major smem ----
        const int cwb = q * 8 + 2 * cql;
        const float c2a = sm[C2S + cwb];
        const float c2b = sm[C2S + cwb + 1];
        const int ib = v0 + cwb;
        #pragma unroll
        for (int mb = 0; mb < 2; mb++) {
            const float* sv = s[mb];
            float d00 = sqrtf(fmaxf(fmaf(-2.0f, sv[0], x2r[mb][0] + c2a), 0.0f));
            float d01 = sqrtf(fmaxf(fmaf(-2.0f, sv[1], x2r[mb][0] + c2b), 0.0f));
            float d10 = sqrtf(fmaxf(fmaf(-2.0f, sv[2], x2r[mb][1] + c2a), 0.0f));
            float d11 = sqrtf(fmaxf(fmaf(-2.0f, sv[3], x2r[mb][1] + c2b), 0.0f));

            if (d00 < mind[mb][0]) { mind[mb][0] = d00; mini[mb][0] = ib; }
            if (d01 < mind[mb][0]) { mind[mb][0] = d01; mini[mb][0] = ib + 1; }
            if (d10 < mind[mb][1]) { mind[mb][1] = d10; mini[mb][1] = ib; }
            if (d11 < mind[mb][1]) { mind[mb][1] = d11; mini[mb][1] = ib + 1; }

            float w00 = d00 + EPSF, w01 = d01 + EPSF;
            float w10 = d10 + EPSF, w11 = d11 + EPSF;
            wsum[mb][0] += w00 + w01;
            wsum[mb][1] += w10 + w11;

            int row = g * 32 + mb * 16 + r0l;
            sm[WB + cwb * 136 + row]           = __uint_as_float(tf32_rna(w00));
            sm[WB + (cwb + 1) * 136 + row]     = __uint_as_float(tf32_rna(w01));
            sm[WB + cwb * 136 + row + 8]       = __uint_as_float(tf32_rna(w10));
            sm[WB + (cwb + 1) * 136 + row + 8] = __uint_as_float(tf32_rna(w11));
        }
        __syncthreads();   // WB complete

        // ---- GEMM2: E[32 x 32] += W[32 x 32] * C[32 x cols q*32..] ----
        #pragma unroll
        for (int kt2 = 0; kt2 < 4; kt2++) {
            const int kk = kt2 * 8 + cql;
            uint32_t a[2][4];
            #pragma unroll
            for (int mb = 0; mb < 2; mb++) {
                int row = g * 32 + mb * 16 + r0l;
                a[mb][0] = fbits(sm[WB + kk * 136 + row]);
                a[mb][1] = fbits(sm[WB + kk * 136 + row + 8]);
                a[mb][2] = fbits(sm[WB + (kk + 4) * 136 + row]);
                a[mb][3] = fbits(sm[WB + (kk + 4) * 136 + row + 8]);
            }
            #pragma unroll
            for (int nt2 = 0; nt2 < 4; nt2++) {
                int col = q * 32 + nt2 * 8 + r0l;
                uint32_t b0 = fbits(sm[CH + kk * 132 + col]);
                uint32_t b1 = fbits(sm[CH + (kk + 4) * 132 + col]);
                mma8(e[0][nt2], a[0], b0, b1);
                mma8(e[1][nt2], a[1], b0, b1);
            }
        }
    }

    // ---- final reduction across the 4 q-splits ----
    __syncthreads();
    #pragma unroll
    for (int mb = 0; mb < 2; mb++)
        #pragma unroll
        for (int r = 0; r < 2; r++) {
            int row = g * 32 + mb * 16 + r0l + r * 8;
            int bi  = row * 16 + q * 4 + cql;
            sm[RS_SUM  + bi] = wsum[mb][r];
            sm[RS_MIND + bi] = mind[mb][r];
            ((int*)sm)[RS_MINI + bi] = mini[mb][r];
        }
    __syncthreads();
    if (t < MCTA) {
        float ssum = 0.0f, bd = 3.4e38f;
        int bi = 1 << 30;
        #pragma unroll
        for (int j = 0; j < 16; j++) {
            ssum += sm[RS_SUM + t * 16 + j];
            float dj = sm[RS_MIND + t * 16 + j];
            int   ij = ((int*)sm)[RS_MINI + t * 16 + j];
            if (dj < bd || (dj == bd && ij < bi)) { bd = dj; bi = ij; }
        }
        sm[RINV + t] = 1.0f / ssum;
        if (out_idx != nullptr) out_idx[m0 + t] = (float)bi;
    }
    __syncthreads();

    // ---- embed output ----
    #pragma unroll
    for (int mb = 0; mb < 2; mb++) {
        int row0 = g * 32 + mb * 16 + r0l;
        float inv0 = sm[RINV + row0];
        float inv1 = sm[RINV + row0 + 8];
        #pragma unroll
        for (int nt2 = 0; nt2 < 4; nt2++) {
            int col = q * 32 + nt2 * 8 + 2 * cql;
            float2 o0 = make_float2(e[mb][nt2][0] * inv0, e[mb][nt2][1] * inv0);
            float2 o1 = make_float2(e[mb][nt2][2] * inv1, e[mb][nt2][3] * inv1);
            *(float2*)(out_embed + (size_t)(m0 + row0) * D128 + col)     = o0;
            *(float2*)(out_embed + (size_t)(m0 + row0 + 8) * D128 + col) = o1;
        }
    }
}

extern "C" void kernel_launch(void* const* d_in, const int* in_sizes, int n_in,
                              void* d_out, int out_size) {
    const float* x  = (const float*)d_in[0];
    const float* cb = (const float*)d_in[1];
    int n = in_sizes[0] / D128;   // 16384
    int v = in_sizes[1] / D128;   // 8192
    float* out  = (float*)d_out;
    float* oidx = ((long long)out_size >= (long long)n * D128 + n)
                      ? out + (size_t)n * D128 : nullptr;

    int nblocks = ((n + v) * 32 + 255) / 256;
    norms_kernel<<<nblocks, 256>>>(x, cb, n, v);

    cudaFuncSetAttribute(softvq_mma, cudaFuncAttributeMaxDynamicSharedMemorySize,
                         SMEM_FLOATS * sizeof(float));
    softvq_mma<<<n / MCTA, THR, SMEM_FLOATS * sizeof(float)>>>(x, cb, out, oidx, n, v);
}